// round 1
// baseline (speedup 1.0000x reference)
#include <cuda_runtime.h>
#include <math.h>
#include <stdint.h>

#define TT 512
#define BB 64
#define KIN 1024
#define HH 1024
#define GG 4096   // 4*H

// ------------------------------------------------------------------
// Scratch (device globals: allocation is forbidden in kernel_launch)
// ------------------------------------------------------------------
__device__ float    g_x4[(size_t)TT * BB * GG];   // 512 MB: precomputed X@Wx^T + b
__device__ float    g_cbuf[2][BB * HH];           // double-buffered cell state
__device__ unsigned g_bar;                        // grid barrier counter

// ------------------------------------------------------------------
// Init kernel: reset barrier, seed c-buffer with c0 (runs every replay)
// ------------------------------------------------------------------
__global__ void init_kernel(const float* __restrict__ c0) {
    int idx = blockIdx.x * blockDim.x + threadIdx.x;
    if (idx == 0) g_bar = 0u;
    if (idx < BB * HH) g_cbuf[0][idx] = c0[idx];
}

// ------------------------------------------------------------------
// X4 GEMM: C[m][n] = sum_k X[m][k] * Wx[n][k] + bias[n]
// M=32768, N=4096, K=1024.  128x128x8 tiles, 256 thr, 8x8 microtile.
// ------------------------------------------------------------------
__global__ void __launch_bounds__(256, 2) x4_gemm_kernel(
    const float* __restrict__ A,     // X  [32768][1024]
    const float* __restrict__ W,     // Wx [4096][1024]
    const float* __restrict__ bias)  // [4096]
{
    __shared__ float As[8][128];
    __shared__ float Bs[8][128];

    const int tid  = threadIdx.x;
    const int m0   = blockIdx.y * 128;
    const int n0   = blockIdx.x * 128;
    const int lrow = tid >> 1;
    const int lk4  = (tid & 1) * 4;
    const float* aptr = A + (size_t)(m0 + lrow) * KIN + lk4;
    const float* bptr = W + (size_t)(n0 + lrow) * KIN + lk4;
    const int tx = tid & 15;
    const int ty = tid >> 4;

    float acc[8][8];
#pragma unroll
    for (int r = 0; r < 8; ++r)
#pragma unroll
        for (int c = 0; c < 8; ++c) acc[r][c] = 0.f;

    for (int kb = 0; kb < KIN; kb += 8) {
        float4 av = *reinterpret_cast<const float4*>(aptr + kb);
        float4 bv = *reinterpret_cast<const float4*>(bptr + kb);
        __syncthreads();
        As[lk4 + 0][lrow] = av.x; As[lk4 + 1][lrow] = av.y;
        As[lk4 + 2][lrow] = av.z; As[lk4 + 3][lrow] = av.w;
        Bs[lk4 + 0][lrow] = bv.x; Bs[lk4 + 1][lrow] = bv.y;
        Bs[lk4 + 2][lrow] = bv.z; Bs[lk4 + 3][lrow] = bv.w;
        __syncthreads();
#pragma unroll
        for (int k = 0; k < 8; ++k) {
            float4 a0 = *reinterpret_cast<const float4*>(&As[k][ty * 8]);
            float4 a1 = *reinterpret_cast<const float4*>(&As[k][ty * 8 + 4]);
            float4 b0 = *reinterpret_cast<const float4*>(&Bs[k][tx * 8]);
            float4 b1 = *reinterpret_cast<const float4*>(&Bs[k][tx * 8 + 4]);
            float ar[8] = {a0.x, a0.y, a0.z, a0.w, a1.x, a1.y, a1.z, a1.w};
            float br[8] = {b0.x, b0.y, b0.z, b0.w, b1.x, b1.y, b1.z, b1.w};
#pragma unroll
            for (int r = 0; r < 8; ++r)
#pragma unroll
                for (int c = 0; c < 8; ++c)
                    acc[r][c] += ar[r] * br[c];
        }
    }

    float bv8[8];
#pragma unroll
    for (int c = 0; c < 8; ++c) bv8[c] = bias[n0 + tx * 8 + c];
#pragma unroll
    for (int r = 0; r < 8; ++r) {
        float* crow = g_x4 + (size_t)(m0 + ty * 8 + r) * GG + n0 + tx * 8;
        float4 v0 = make_float4(acc[r][0] + bv8[0], acc[r][1] + bv8[1],
                                acc[r][2] + bv8[2], acc[r][3] + bv8[3]);
        float4 v1 = make_float4(acc[r][4] + bv8[4], acc[r][5] + bv8[5],
                                acc[r][6] + bv8[6], acc[r][7] + bv8[7]);
        *reinterpret_cast<float4*>(crow)     = v0;
        *reinterpret_cast<float4*>(crow + 4) = v1;
    }
}

// ------------------------------------------------------------------
// Persistent recurrence kernel
// 128 CTAs x 128 threads. CTA ci owns j-cols [ci*8, ci*8+8) for all 4
// gates => 32 rows of Wh held in SMEM (transposed) for all 512 steps.
// ------------------------------------------------------------------
struct SmemLayout {
    float wsT[1024][32];   // Wh slice, transposed: wsT[k][cc]  (128 KB)
    float csT[128][64];    // c chunk, transposed:  csT[k][b]   (32 KB)
    float pre[64][33];     // staged pre-activations (padded)   (8.25 KB)
    float hs[64][8];       // h state for owned cols            (2 KB)
    float cs_own[64][8];   // c state for owned cols            (2 KB)
};

extern __shared__ char smem_raw[];

__device__ __forceinline__ void grid_sync(unsigned& target) {
    __threadfence();
    __syncthreads();
    target += gridDim.x;
    if (threadIdx.x == 0) {
        atomicAdd(&g_bar, 1u);
        volatile unsigned* p = &g_bar;
        while (*p < target) { __nanosleep(64); }
    }
    __syncthreads();
}

__global__ void __launch_bounds__(128, 1) lstm_persistent(
    const float* __restrict__ h0, const float* __restrict__ c0,
    const int* __restrict__ mask, const float* __restrict__ Wh,
    float* __restrict__ out)
{
    SmemLayout& S = *reinterpret_cast<SmemLayout*>(smem_raw);
    const int tid   = threadIdx.x;
    const int ci    = blockIdx.x;        // 0..127
    const int jbase = ci * 8;

    // ---- load Wh slice transposed: wsT[k][cc] = Wh[q*H + jbase + jj][k]
    {
        int cc = tid >> 2;               // 0..31 (4 threads per row)
        int q = cc >> 3, jj = cc & 7;
        const float* wrow = Wh + ((size_t)(q * HH + jbase + jj)) * HH;
        int koff = (tid & 3) * 256;
#pragma unroll 4
        for (int k = 0; k < 256; k += 4) {
            float4 w = *reinterpret_cast<const float4*>(wrow + koff + k);
            S.wsT[koff + k + 0][cc] = w.x;
            S.wsT[koff + k + 1][cc] = w.y;
            S.wsT[koff + k + 2][cc] = w.z;
            S.wsT[koff + k + 3][cc] = w.w;
        }
    }
    // ---- init h / own-c state
    for (int p = tid; p < 512; p += 128) {
        int b = p >> 3, jj = p & 7;
        S.hs[b][jj]     = h0[b * HH + jbase + jj];
        S.cs_own[b][jj] = c0[b * HH + jbase + jj];
    }
    __syncthreads();

    const int i16 = tid >> 3;   // 0..15 : b-group (4 rows)
    const int j8  = tid & 7;    // 0..7  : cc-group (4 cols)
    unsigned bar_target = 0;

    for (int t = 0; t < TT; ++t) {
        const float* cbuf_r = g_cbuf[t & 1];
        float*       cbuf_w = g_cbuf[(t + 1) & 1];

        // ---- prefetch x4 + mask for this step (hides DRAM under GEMM)
        float x4v[4][4];
        int   mv[4];
#pragma unroll
        for (int r = 0; r < 4; ++r) {
            int p = tid + 128 * r;
            int b = p >> 3, jj = p & 7;
            const float* xp = g_x4 + ((size_t)t * BB + b) * GG + jbase + jj;
            x4v[r][0] = xp[0];
            x4v[r][1] = xp[HH];
            x4v[r][2] = xp[2 * HH];
            x4v[r][3] = xp[3 * HH];
            mv[r] = mask[t * BB + b];
        }

        // ---- GEMM: pre[b][cc] = sum_k c[b][k] * wsT[k][cc]
        float acc[4][4];
#pragma unroll
        for (int r = 0; r < 4; ++r)
#pragma unroll
            for (int c = 0; c < 4; ++c) acc[r][c] = 0.f;

        for (int kb = 0; kb < HH; kb += 128) {
            // stage c chunk transposed (read via L2: data written by peers)
            {
                int b  = tid >> 1;
                int kh = (tid & 1) * 64;
                const float4* src =
                    reinterpret_cast<const float4*>(cbuf_r + b * HH + kb + kh);
#pragma unroll
                for (int kk4 = 0; kk4 < 16; ++kk4) {
                    float4 v = __ldcg(src + kk4);
                    int k = kh + kk4 * 4;
                    S.csT[k + 0][b] = v.x;
                    S.csT[k + 1][b] = v.y;
                    S.csT[k + 2][b] = v.z;
                    S.csT[k + 3][b] = v.w;
                }
            }
            __syncthreads();
#pragma unroll 8
            for (int kk = 0; kk < 128; ++kk) {
                float4 cv = *reinterpret_cast<const float4*>(&S.csT[kk][i16 * 4]);
                float4 wv = *reinterpret_cast<const float4*>(&S.wsT[kb + kk][j8 * 4]);
                acc[0][0] += cv.x * wv.x; acc[0][1] += cv.x * wv.y;
                acc[0][2] += cv.x * wv.z; acc[0][3] += cv.x * wv.w;
                acc[1][0] += cv.y * wv.x; acc[1][1] += cv.y * wv.y;
                acc[1][2] += cv.y * wv.z; acc[1][3] += cv.y * wv.w;
                acc[2][0] += cv.z * wv.x; acc[2][1] += cv.z * wv.y;
                acc[2][2] += cv.z * wv.z; acc[2][3] += cv.z * wv.w;
                acc[3][0] += cv.w * wv.x; acc[3][1] += cv.w * wv.y;
                acc[3][2] += cv.w * wv.z; acc[3][3] += cv.w * wv.w;
            }
            __syncthreads();
        }

        // ---- stage pre through smem so gates can gather i/f/o/g
#pragma unroll
        for (int r = 0; r < 4; ++r)
#pragma unroll
            for (int c = 0; c < 4; ++c)
                S.pre[i16 * 4 + r][j8 * 4 + c] = acc[r][c];
        __syncthreads();

        // ---- gates + state update + outputs
#pragma unroll
        for (int r = 0; r < 4; ++r) {
            int p = tid + 128 * r;
            int b = p >> 3, jj = p & 7;
            int jcol = jbase + jj;

            float pi = S.pre[b][jj]      + x4v[r][0];
            float pf = S.pre[b][8 + jj]  + x4v[r][1];
            float po = S.pre[b][16 + jj] + x4v[r][2];
            float pg = S.pre[b][24 + jj] + x4v[r][3];

            float ig = 1.f / (1.f + __expf(-pi));
            float fg = 1.f / (1.f + __expf(-pf));
            float og = 1.f / (1.f + __expf(-po));
            float gg = tanhf(pg);

            float cold = S.cs_own[b][jj];
            float cnew = fg * cold + ig * gg;
            float hold = S.hs[b][jj];
            int   m    = mv[r];
            float hnew = m ? (og * tanhf(cnew)) : hold;
            float cpub = m ? cnew : cold;

            S.hs[b][jj]     = hnew;
            S.cs_own[b][jj] = cpub;
            cbuf_w[b * HH + jcol] = cpub;
            out[((size_t)t * BB + b) * HH + jcol] = hnew;
        }

        grid_sync(bar_target);
    }

    // ---- finals: h_last, c_last appended after hiddens
    const size_t hid_elems = (size_t)TT * BB * HH;
    for (int p = tid; p < 512; p += 128) {
        int b = p >> 3, jj = p & 7;
        out[hid_elems + b * HH + jbase + jj]           = S.hs[b][jj];
        out[hid_elems + BB * HH + b * HH + jbase + jj] = S.cs_own[b][jj];
    }
}

// ------------------------------------------------------------------
// Launch
// ------------------------------------------------------------------
extern "C" void kernel_launch(void* const* d_in, const int* in_sizes, int n_in,
                              void* d_out, int out_size) {
    const float* X    = (const float*)d_in[0];
    const float* h0   = (const float*)d_in[1];
    const float* c0   = (const float*)d_in[2];
    const int*   mask = (const int*)d_in[3];
    const float* Wx   = (const float*)d_in[4];
    const float* Wh   = (const float*)d_in[5];
    const float* bias = (const float*)d_in[6];
    float* out = (float*)d_out;

    cudaFuncSetAttribute(lstm_persistent,
                         cudaFuncAttributeMaxDynamicSharedMemorySize,
                         (int)sizeof(SmemLayout));

    init_kernel<<<256, 256>>>(c0);

    dim3 g(GG / 128, (TT * BB) / 128);   // (32, 256)
    x4_gemm_kernel<<<g, 256>>>(X, Wx, bias);

    lstm_persistent<<<128, 128, sizeof(SmemLayout)>>>(h0, c0, mask, Wh, out);
}

// round 2
// speedup vs baseline: 1.8659x; 1.8659x over previous
#include <cuda_runtime.h>
#include <cuda_bf16.h>
#include <math.h>
#include <stdint.h>

#define TT 512
#define BB 64
#define KIN 1024
#define HH 1024
#define GG 4096   // 4*H

// ------------------------------------------------------------------
// Scratch (device globals: allocation is forbidden in kernel_launch)
// ------------------------------------------------------------------
__device__ float         g_x4[(size_t)TT * BB * GG];     // 512 MB fp32: X@Wx^T + b
__device__ __nv_bfloat16 g_xh[(size_t)TT * BB * KIN];    // X hi split
__device__ __nv_bfloat16 g_xl[(size_t)TT * BB * KIN];    // X lo split
__device__ __nv_bfloat16 g_wxh[(size_t)GG * KIN];        // Wx hi
__device__ __nv_bfloat16 g_wxl[(size_t)GG * KIN];        // Wx lo
__device__ unsigned      g_cpk[2][BB * HH];              // packed (hi<<16)|lo cell state
__device__ unsigned      g_bar;

// ------------------------------------------------------------------
// helpers
// ------------------------------------------------------------------
__device__ __forceinline__ unsigned pack_split(float v) {
    __nv_bfloat16 h = __float2bfloat16_rn(v);
    float r = v - __bfloat162float(h);
    __nv_bfloat16 l = __float2bfloat16_rn(r);
    return ((unsigned)__bfloat16_as_ushort(h) << 16) |
           (unsigned)__bfloat16_as_ushort(l);
}

__device__ __forceinline__ uint32_t sh_addr(const void* p) {
    return (uint32_t)__cvta_generic_to_shared(p);
}

#define LDSM_X4(r, addr)                                                     \
    asm volatile("ldmatrix.sync.aligned.m8n8.x4.shared.b16 {%0,%1,%2,%3}, [%4];" \
                 : "=r"((r)[0]), "=r"((r)[1]), "=r"((r)[2]), "=r"((r)[3])    \
                 : "r"(addr))

#define LDSM_X2(r, addr)                                                     \
    asm volatile("ldmatrix.sync.aligned.m8n8.x2.shared.b16 {%0,%1}, [%2];"   \
                 : "=r"((r)[0]), "=r"((r)[1]) : "r"(addr))

#define MMA_BF16(d, a, b0, b1)                                               \
    asm volatile("mma.sync.aligned.m16n8k16.row.col.f32.bf16.bf16.f32 "      \
                 "{%0,%1,%2,%3}, {%4,%5,%6,%7}, {%8,%9}, {%0,%1,%2,%3};"     \
                 : "+f"((d)[0]), "+f"((d)[1]), "+f"((d)[2]), "+f"((d)[3])    \
                 : "r"((a)[0]), "r"((a)[1]), "r"((a)[2]), "r"((a)[3]),       \
                   "r"(b0), "r"(b1))

// ------------------------------------------------------------------
// Init: barrier + seed packed c buffer
// ------------------------------------------------------------------
__global__ void init_kernel(const float* __restrict__ c0) {
    int idx = blockIdx.x * blockDim.x + threadIdx.x;
    if (idx == 0) g_bar = 0u;
    if (idx < BB * HH) g_cpk[0][idx] = pack_split(c0[idx]);
}

// ------------------------------------------------------------------
// Split kernels: fp32 -> (hi, lo) bf16
// ------------------------------------------------------------------
__device__ __forceinline__ void split4_store(const float4* src, uint2* dh,
                                             uint2* dl, int i) {
    float4 v = src[i];
    unsigned p0 = pack_split(v.x), p1 = pack_split(v.y);
    unsigned p2 = pack_split(v.z), p3 = pack_split(v.w);
    dh[i] = make_uint2(__byte_perm(p0, p1, 0x7632), __byte_perm(p2, p3, 0x7632));
    dl[i] = make_uint2(__byte_perm(p0, p1, 0x5410), __byte_perm(p2, p3, 0x5410));
}

__global__ void split_x_kernel(const float* __restrict__ X) {
    int i = blockIdx.x * blockDim.x + threadIdx.x;
    const int n4 = TT * BB * KIN / 4;
    if (i < n4)
        split4_store((const float4*)X, (uint2*)g_xh, (uint2*)g_xl, i);
}

__global__ void split_w_kernel(const float* __restrict__ W) {
    int i = blockIdx.x * blockDim.x + threadIdx.x;
    const int n4 = GG * KIN / 4;
    if (i < n4)
        split4_store((const float4*)W, (uint2*)g_wxh, (uint2*)g_wxl, i);
}

// ------------------------------------------------------------------
// X4 GEMM via tensor cores (bf16 split, 3 phase products)
// C[32768][4096] = X[32768][1024] @ Wx[4096][1024]^T + bias
// 128x128 tile, BK=64, 256 threads, warp tile 32x64
// ------------------------------------------------------------------
__global__ void __launch_bounds__(256) x4_mma_kernel(const float* __restrict__ bias) {
    __shared__ __align__(16) __nv_bfloat16 SA[128][72];
    __shared__ __align__(16) __nv_bfloat16 SB[128][72];

    const int tid  = threadIdx.x;
    const int lane = tid & 31;
    const int wid  = tid >> 5;
    const int wm   = wid >> 1;   // 0..3 -> m offset 32*wm
    const int wn   = wid & 1;    // 0..1 -> n offset 64*wn
    const int m0   = blockIdx.y * 128;
    const int n0   = blockIdx.x * 128;

    float acc[2][8][4];
#pragma unroll
    for (int mi = 0; mi < 2; ++mi)
#pragma unroll
        for (int nt = 0; nt < 8; ++nt)
#pragma unroll
            for (int e = 0; e < 4; ++e) acc[mi][nt][e] = 0.f;

    const uint32_t a_base =
        sh_addr(&SA[wm * 32 + (lane & 15)][(lane >> 4) * 8]);
    const uint32_t b_base =
        sh_addr(&SB[wn * 64 + (lane & 7)][((lane >> 3) & 1) * 8]);

    // prefetch chunk 0
    uint4 av[4], bv[4];
    {
        const __nv_bfloat16* Asrc = g_xh;
        const __nv_bfloat16* Bsrc = g_wxh;
#pragma unroll
        for (int j = 0; j < 4; ++j) {
            int u = tid + 256 * j;
            int row = u >> 3, seg = u & 7;
            av[j] = *(const uint4*)(Asrc + (size_t)(m0 + row) * KIN + seg * 8);
            bv[j] = *(const uint4*)(Bsrc + (size_t)(n0 + row) * KIN + seg * 8);
        }
    }

    for (int kc2 = 0; kc2 < 48; ++kc2) {
        __syncthreads();
#pragma unroll
        for (int j = 0; j < 4; ++j) {
            int u = tid + 256 * j;
            int row = u >> 3, seg = u & 7;
            *(uint4*)&SA[row][seg * 8] = av[j];
            *(uint4*)&SB[row][seg * 8] = bv[j];
        }
        __syncthreads();

        // prefetch next chunk while computing
        if (kc2 < 47) {
            int nk = kc2 + 1;
            int p  = nk >> 4;
            int kb = (nk & 15) << 6;
            const __nv_bfloat16* Asrc = (p == 1) ? g_xl : g_xh;
            const __nv_bfloat16* Bsrc = (p == 2) ? g_wxl : g_wxh;
#pragma unroll
            for (int j = 0; j < 4; ++j) {
                int u = tid + 256 * j;
                int row = u >> 3, seg = u & 7;
                av[j] = *(const uint4*)(Asrc + (size_t)(m0 + row) * KIN + kb + seg * 8);
                bv[j] = *(const uint4*)(Bsrc + (size_t)(n0 + row) * KIN + kb + seg * 8);
            }
        }

#pragma unroll
        for (int ks = 0; ks < 4; ++ks) {
            uint32_t a[2][4];
            LDSM_X4(a[0], a_base + (uint32_t)(ks * 16) * 2);
            LDSM_X4(a[1], a_base + (uint32_t)(16 * 72 + ks * 16) * 2);
            uint32_t b[8][2];
#pragma unroll
            for (int nt = 0; nt < 8; ++nt)
                LDSM_X2(b[nt], b_base + (uint32_t)(nt * 8 * 72 + ks * 16) * 2);
#pragma unroll
            for (int mi = 0; mi < 2; ++mi)
#pragma unroll
                for (int nt = 0; nt < 8; ++nt)
                    MMA_BF16(acc[mi][nt], a[mi], b[nt][0], b[nt][1]);
        }
    }

    // epilogue: bias + store fp32
    const int r0  = m0 + wm * 32 + (lane >> 2);
    const int c0c = n0 + wn * 64 + (lane & 3) * 2;
#pragma unroll
    for (int nt = 0; nt < 8; ++nt) {
        float2 bv2 = *(const float2*)&bias[c0c + nt * 8];
#pragma unroll
        for (int mi = 0; mi < 2; ++mi) {
            float* o = g_x4 + (size_t)(r0 + mi * 16) * GG + c0c + nt * 8;
            float2 v0 = make_float2(acc[mi][nt][0] + bv2.x, acc[mi][nt][1] + bv2.y);
            float2 v1 = make_float2(acc[mi][nt][2] + bv2.x, acc[mi][nt][3] + bv2.y);
            *(float2*)o            = v0;
            *(float2*)(o + 8 * GG) = v1;
        }
    }
}

// ------------------------------------------------------------------
// Persistent recurrence kernel (tensor-core step GEMM)
// 128 CTAs x 128 threads. CTA ci owns N-slice of 32 (8 cols x 4 gates).
// ------------------------------------------------------------------
struct RSmem {
    __nv_bfloat16 whH[32][1032];   // 66048 B
    __nv_bfloat16 whL[32][1032];   // 66048 B
    __nv_bfloat16 cH[64][264];     // 33792 B  (K chunk = 256)
    __nv_bfloat16 cL[64][264];     // 33792 B
    float pre[64][36];             //  9216 B
    float hs[64][8];               //  2048 B
    float cs[64][8];               //  2048 B
};                                 // total 212992 B

extern __shared__ char smem_raw[];

__device__ __forceinline__ void grid_sync(unsigned& target) {
    __threadfence();
    __syncthreads();
    target += gridDim.x;
    if (threadIdx.x == 0) {
        atomicAdd(&g_bar, 1u);
        volatile unsigned* p = &g_bar;
        while (*p < target) { __nanosleep(64); }
    }
    __syncthreads();
}

__global__ void __launch_bounds__(128, 1) lstm_persistent(
    const float* __restrict__ h0, const float* __restrict__ c0,
    const int* __restrict__ mask, const float* __restrict__ Wh,
    float* __restrict__ out)
{
    RSmem& S = *reinterpret_cast<RSmem*>(smem_raw);
    const int tid   = threadIdx.x;
    const int lane  = tid & 31;
    const int w     = tid >> 5;          // warp 0..3 -> m16 tile
    const int ci    = blockIdx.x;
    const int jbase = ci * 8;

    // ---- load Wh slice, split to bf16 hi/lo (resident all steps)
    for (int i = 0; i < 256; ++i) {
        int e = i * 128 + tid;           // 32768 elements
        int n = e >> 10, k = e & 1023;
        int grow = (n >> 3) * HH + jbase + (n & 7);
        float v = Wh[(size_t)grow * HH + k];
        __nv_bfloat16 h = __float2bfloat16_rn(v);
        float r = v - __bfloat162float(h);
        S.whH[n][k] = h;
        S.whL[n][k] = __float2bfloat16_rn(r);
    }
    // ---- init h / own-c state
    for (int p = tid; p < 512; p += 128) {
        int b = p >> 3, jj = p & 7;
        S.hs[b][jj] = h0[b * HH + jbase + jj];
        S.cs[b][jj] = c0[b * HH + jbase + jj];
    }
    __syncthreads();

    const uint32_t aH_base = sh_addr(&S.cH[w * 16 + (lane & 15)][(lane >> 4) * 8]);
    const uint32_t aL_base = sh_addr(&S.cL[w * 16 + (lane & 15)][(lane >> 4) * 8]);
    const uint32_t bH_base = sh_addr(&S.whH[lane & 7][(lane >> 3) * 8]);
    const uint32_t bL_base = sh_addr(&S.whL[lane & 7][(lane >> 3) * 8]);

    unsigned bar_target = 0;

    for (int t = 0; t < TT; ++t) {
        // ---- prefetch x4 + mask
        float x4v[4][4];
        int   mv[4];
#pragma unroll
        for (int r = 0; r < 4; ++r) {
            int p = tid + 128 * r;
            int b = p >> 3, jj = p & 7;
            const float* xp = g_x4 + ((size_t)t * BB + b) * GG + jbase + jj;
            x4v[r][0] = xp[0];
            x4v[r][1] = xp[HH];
            x4v[r][2] = xp[2 * HH];
            x4v[r][3] = xp[3 * HH];
            mv[r] = mask[t * BB + b];
        }

        const uint4* csrc = (const uint4*)(g_cpk[t & 1]);   // [64][256] uint4
        float acc[4][4];
#pragma unroll
        for (int nt = 0; nt < 4; ++nt)
#pragma unroll
            for (int e = 0; e < 4; ++e) acc[nt][e] = 0.f;

        for (int kc = 0; kc < 4; ++kc) {
            __syncthreads();   // previous chunk's mma done before overwrite
            // ---- unpack packed c chunk into cH / cL (bf16)
#pragma unroll 4
            for (int j2 = 0; j2 < 32; ++j2) {
                int u = tid + 128 * j2;
                int row = u >> 6, k4 = u & 63;
                uint4 v = __ldcg(&csrc[row * 256 + kc * 64 + k4]);
                unsigned h01 = __byte_perm(v.x, v.y, 0x7632);
                unsigned l01 = __byte_perm(v.x, v.y, 0x5410);
                unsigned h23 = __byte_perm(v.z, v.w, 0x7632);
                unsigned l23 = __byte_perm(v.z, v.w, 0x5410);
                *(uint2*)&S.cH[row][k4 * 4] = make_uint2(h01, h23);
                *(uint2*)&S.cL[row][k4 * 4] = make_uint2(l01, l23);
            }
            __syncthreads();

            // ---- tensor-core products over this K chunk
#pragma unroll
            for (int g = 0; g < 8; ++g) {
                uint32_t ah0[4], ah1[4], al0[4], al1[4];
                LDSM_X4(ah0, aH_base + (uint32_t)(g * 32) * 2);
                LDSM_X4(ah1, aH_base + (uint32_t)(g * 32 + 16) * 2);
                LDSM_X4(al0, aL_base + (uint32_t)(g * 32) * 2);
                LDSM_X4(al1, aL_base + (uint32_t)(g * 32 + 16) * 2);
                const uint32_t koff = (uint32_t)((kc * 256 + g * 32) * 2);
#pragma unroll
                for (int nt = 0; nt < 4; ++nt) {
                    uint32_t bh[4], bl[4];
                    LDSM_X4(bh, bH_base + (uint32_t)(nt * 8 * 1032) * 2 + koff);
                    LDSM_X4(bl, bL_base + (uint32_t)(nt * 8 * 1032) * 2 + koff);
                    MMA_BF16(acc[nt], ah0, bh[0], bh[1]);
                    MMA_BF16(acc[nt], ah1, bh[2], bh[3]);
                    MMA_BF16(acc[nt], al0, bh[0], bh[1]);
                    MMA_BF16(acc[nt], al1, bh[2], bh[3]);
                    MMA_BF16(acc[nt], ah0, bl[0], bl[1]);
                    MMA_BF16(acc[nt], ah1, bl[2], bl[3]);
                }
            }
        }

        // ---- stage pre-activations through smem
        {
            int prow = w * 16 + (lane >> 2);
            int pcol = (lane & 3) * 2;
#pragma unroll
            for (int nt = 0; nt < 4; ++nt) {
                S.pre[prow][nt * 8 + pcol]         = acc[nt][0];
                S.pre[prow][nt * 8 + pcol + 1]     = acc[nt][1];
                S.pre[prow + 8][nt * 8 + pcol]     = acc[nt][2];
                S.pre[prow + 8][nt * 8 + pcol + 1] = acc[nt][3];
            }
        }
        __syncthreads();

        // ---- gates + state update + publish
        unsigned* cdst = g_cpk[(t + 1) & 1];
#pragma unroll
        for (int r = 0; r < 4; ++r) {
            int p = tid + 128 * r;
            int b = p >> 3, jj = p & 7;
            int jcol = jbase + jj;

            float pi = S.pre[b][jj]      + x4v[r][0];
            float pf = S.pre[b][8 + jj]  + x4v[r][1];
            float po = S.pre[b][16 + jj] + x4v[r][2];
            float pg = S.pre[b][24 + jj] + x4v[r][3];

            float ig = 1.f / (1.f + __expf(-pi));
            float fg = 1.f / (1.f + __expf(-pf));
            float og = 1.f / (1.f + __expf(-po));
            float gg = tanhf(pg);

            float cold = S.cs[b][jj];
            float cnew = fg * cold + ig * gg;
            float hold = S.hs[b][jj];
            int   m    = mv[r];
            float hnew = m ? (og * tanhf(cnew)) : hold;
            float cpub = m ? cnew : cold;

            S.hs[b][jj] = hnew;
            S.cs[b][jj] = cpub;
            cdst[b * HH + jcol] = pack_split(cpub);
            out[((size_t)t * BB + b) * HH + jcol] = hnew;
        }

        grid_sync(bar_target);
    }

    // ---- finals: h_last, c_last appended after hiddens
    const size_t hid_elems = (size_t)TT * BB * HH;
    for (int p = tid; p < 512; p += 128) {
        int b = p >> 3, jj = p & 7;
        out[hid_elems + b * HH + jbase + jj]           = S.hs[b][jj];
        out[hid_elems + BB * HH + b * HH + jbase + jj] = S.cs[b][jj];
    }
}

// ------------------------------------------------------------------
// Launch
// ------------------------------------------------------------------
extern "C" void kernel_launch(void* const* d_in, const int* in_sizes, int n_in,
                              void* d_out, int out_size) {
    const float* X    = (const float*)d_in[0];
    const float* h0   = (const float*)d_in[1];
    const float* c0   = (const float*)d_in[2];
    const int*   mask = (const int*)d_in[3];
    const float* Wx   = (const float*)d_in[4];
    const float* Wh   = (const float*)d_in[5];
    const float* bias = (const float*)d_in[6];
    float* out = (float*)d_out;

    cudaFuncSetAttribute(lstm_persistent,
                         cudaFuncAttributeMaxDynamicSharedMemorySize,
                         (int)sizeof(RSmem));

    init_kernel<<<256, 256>>>(c0);

    split_x_kernel<<<(TT * BB * KIN / 4 + 255) / 256, 256>>>(X);
    split_w_kernel<<<(GG * KIN / 4 + 255) / 256, 256>>>(Wx);

    dim3 g(GG / 128, (TT * BB) / 128);   // (32, 256)
    x4_mma_kernel<<<g, 256>>>(bias);

    lstm_persistent<<<128, 128, sizeof(RSmem)>>>(h0, c0, mask, Wh, out);
}

// round 3
// speedup vs baseline: 1.8662x; 1.0002x over previous
#include <cuda_runtime.h>
#include <cuda_bf16.h>
#include <math.h>
#include <stdint.h>

#define TT 512
#define BB 64
#define KIN 1024
#define HH 1024
#define GG 4096   // 4*H

// ------------------------------------------------------------------
// Scratch (device globals: allocation is forbidden in kernel_launch)
// ------------------------------------------------------------------
__device__ float         g_x4[(size_t)TT * BB * GG];     // 512 MB fp32: X@Wx^T + b
__device__ __nv_bfloat16 g_xh[(size_t)TT * BB * KIN];    // X hi split
__device__ __nv_bfloat16 g_xl[(size_t)TT * BB * KIN];    // X lo split
__device__ __nv_bfloat16 g_wxh[(size_t)GG * KIN];        // Wx hi
__device__ __nv_bfloat16 g_wxl[(size_t)GG * KIN];        // Wx lo
__device__ unsigned      g_cpk[2][BB * HH];              // packed (hi<<16)|lo cell state
__device__ unsigned      g_bar;

// ------------------------------------------------------------------
// helpers
// ------------------------------------------------------------------
__device__ __forceinline__ unsigned pack_split(float v) {
    __nv_bfloat16 h = __float2bfloat16_rn(v);
    float r = v - __bfloat162float(h);
    __nv_bfloat16 l = __float2bfloat16_rn(r);
    return ((unsigned)__bfloat16_as_ushort(h) << 16) |
           (unsigned)__bfloat16_as_ushort(l);
}

__device__ __forceinline__ uint32_t sh_addr(const void* p) {
    return (uint32_t)__cvta_generic_to_shared(p);
}

#define LDSM_X4(r, addr)                                                     \
    asm volatile("ldmatrix.sync.aligned.m8n8.x4.shared.b16 {%0,%1,%2,%3}, [%4];" \
                 : "=r"((r)[0]), "=r"((r)[1]), "=r"((r)[2]), "=r"((r)[3])    \
                 : "r"(addr))

#define LDSM_X2(r, addr)                                                     \
    asm volatile("ldmatrix.sync.aligned.m8n8.x2.shared.b16 {%0,%1}, [%2];"   \
                 : "=r"((r)[0]), "=r"((r)[1]) : "r"(addr))

#define MMA_BF16(d, a, b0, b1)                                               \
    asm volatile("mma.sync.aligned.m16n8k16.row.col.f32.bf16.bf16.f32 "      \
                 "{%0,%1,%2,%3}, {%4,%5,%6,%7}, {%8,%9}, {%0,%1,%2,%3};"     \
                 : "+f"((d)[0]), "+f"((d)[1]), "+f"((d)[2]), "+f"((d)[3])    \
                 : "r"((a)[0]), "r"((a)[1]), "r"((a)[2]), "r"((a)[3]),       \
                   "r"(b0), "r"(b1))

// ------------------------------------------------------------------
// Init: barrier + seed packed c buffer
// ------------------------------------------------------------------
__global__ void init_kernel(const float* __restrict__ c0) {
    int idx = blockIdx.x * blockDim.x + threadIdx.x;
    if (idx == 0) g_bar = 0u;
    if (idx < BB * HH) g_cpk[0][idx] = pack_split(c0[idx]);
}

// ------------------------------------------------------------------
// Split kernels: fp32 -> (hi, lo) bf16
// ------------------------------------------------------------------
__device__ __forceinline__ void split4_store(const float4* src, uint2* dh,
                                             uint2* dl, int i) {
    float4 v = src[i];
    unsigned p0 = pack_split(v.x), p1 = pack_split(v.y);
    unsigned p2 = pack_split(v.z), p3 = pack_split(v.w);
    dh[i] = make_uint2(__byte_perm(p0, p1, 0x7632), __byte_perm(p2, p3, 0x7632));
    dl[i] = make_uint2(__byte_perm(p0, p1, 0x5410), __byte_perm(p2, p3, 0x5410));
}

__global__ void split_x_kernel(const float* __restrict__ X) {
    int i = blockIdx.x * blockDim.x + threadIdx.x;
    const int n4 = TT * BB * KIN / 4;
    if (i < n4)
        split4_store((const float4*)X, (uint2*)g_xh, (uint2*)g_xl, i);
}

__global__ void split_w_kernel(const float* __restrict__ W) {
    int i = blockIdx.x * blockDim.x + threadIdx.x;
    const int n4 = GG * KIN / 4;
    if (i < n4)
        split4_store((const float4*)W, (uint2*)g_wxh, (uint2*)g_wxl, i);
}

// ------------------------------------------------------------------
// X4 GEMM via tensor cores (bf16 split, 3 phase products)
// C[32768][4096] = X[32768][1024] @ Wx[4096][1024]^T + bias
// 128x128 tile, BK=64, 256 threads, warp tile 32x64
// ------------------------------------------------------------------
__global__ void __launch_bounds__(256) x4_mma_kernel(const float* __restrict__ bias) {
    __shared__ __align__(16) __nv_bfloat16 SA[128][72];
    __shared__ __align__(16) __nv_bfloat16 SB[128][72];

    const int tid  = threadIdx.x;
    const int lane = tid & 31;
    const int wid  = tid >> 5;
    const int wm   = wid >> 1;   // 0..3 -> m offset 32*wm
    const int wn   = wid & 1;    // 0..1 -> n offset 64*wn
    const int m0   = blockIdx.y * 128;
    const int n0   = blockIdx.x * 128;

    float acc[2][8][4];
#pragma unroll
    for (int mi = 0; mi < 2; ++mi)
#pragma unroll
        for (int nt = 0; nt < 8; ++nt)
#pragma unroll
            for (int e = 0; e < 4; ++e) acc[mi][nt][e] = 0.f;

    const uint32_t a_base =
        sh_addr(&SA[wm * 32 + (lane & 15)][(lane >> 4) * 8]);
    const uint32_t b_base =
        sh_addr(&SB[wn * 64 + (lane & 7)][((lane >> 3) & 1) * 8]);

    // prefetch chunk 0
    uint4 av[4], bv[4];
    {
        const __nv_bfloat16* Asrc = g_xh;
        const __nv_bfloat16* Bsrc = g_wxh;
#pragma unroll
        for (int j = 0; j < 4; ++j) {
            int u = tid + 256 * j;
            int row = u >> 3, seg = u & 7;
            av[j] = *(const uint4*)(Asrc + (size_t)(m0 + row) * KIN + seg * 8);
            bv[j] = *(const uint4*)(Bsrc + (size_t)(n0 + row) * KIN + seg * 8);
        }
    }

    for (int kc2 = 0; kc2 < 48; ++kc2) {
        __syncthreads();
#pragma unroll
        for (int j = 0; j < 4; ++j) {
            int u = tid + 256 * j;
            int row = u >> 3, seg = u & 7;
            *(uint4*)&SA[row][seg * 8] = av[j];
            *(uint4*)&SB[row][seg * 8] = bv[j];
        }
        __syncthreads();

        // prefetch next chunk while computing
        if (kc2 < 47) {
            int nk = kc2 + 1;
            int p  = nk >> 4;
            int kb = (nk & 15) << 6;
            const __nv_bfloat16* Asrc = (p == 1) ? g_xl : g_xh;
            const __nv_bfloat16* Bsrc = (p == 2) ? g_wxl : g_wxh;
#pragma unroll
            for (int j = 0; j < 4; ++j) {
                int u = tid + 256 * j;
                int row = u >> 3, seg = u & 7;
                av[j] = *(const uint4*)(Asrc + (size_t)(m0 + row) * KIN + kb + seg * 8);
                bv[j] = *(const uint4*)(Bsrc + (size_t)(n0 + row) * KIN + kb + seg * 8);
            }
        }

#pragma unroll
        for (int ks = 0; ks < 4; ++ks) {
            uint32_t a[2][4];
            LDSM_X4(a[0], a_base + (uint32_t)(ks * 16) * 2);
            LDSM_X4(a[1], a_base + (uint32_t)(16 * 72 + ks * 16) * 2);
            uint32_t b[8][2];
#pragma unroll
            for (int nt = 0; nt < 8; ++nt)
                LDSM_X2(b[nt], b_base + (uint32_t)(nt * 8 * 72 + ks * 16) * 2);
#pragma unroll
            for (int mi = 0; mi < 2; ++mi)
#pragma unroll
                for (int nt = 0; nt < 8; ++nt)
                    MMA_BF16(acc[mi][nt], a[mi], b[nt][0], b[nt][1]);
        }
    }

    // epilogue: bias + store fp32
    const int r0  = m0 + wm * 32 + (lane >> 2);
    const int c0c = n0 + wn * 64 + (lane & 3) * 2;
#pragma unroll
    for (int nt = 0; nt < 8; ++nt) {
        float2 bv2 = *(const float2*)&bias[c0c + nt * 8];
#pragma unroll
        for (int mi = 0; mi < 2; ++mi) {
            float* o = g_x4 + (size_t)(r0 + mi * 16) * GG + c0c + nt * 8;
            float2 v0 = make_float2(acc[mi][nt][0] + bv2.x, acc[mi][nt][1] + bv2.y);
            float2 v1 = make_float2(acc[mi][nt][2] + bv2.x, acc[mi][nt][3] + bv2.y);
            *(float2*)o            = v0;
            *(float2*)(o + 8 * GG) = v1;
        }
    }
}

// ------------------------------------------------------------------
// Persistent recurrence kernel (tensor-core step GEMM)
// 128 CTAs x 128 threads. CTA ci owns N-slice of 32 (8 cols x 4 gates).
// ------------------------------------------------------------------
struct RSmem {
    __nv_bfloat16 whH[32][1032];   // 66048 B
    __nv_bfloat16 whL[32][1032];   // 66048 B
    __nv_bfloat16 cH[64][264];     // 33792 B  (K chunk = 256)
    __nv_bfloat16 cL[64][264];     // 33792 B
    float pre[64][36];             //  9216 B
    float hs[64][8];               //  2048 B
    float cs[64][8];               //  2048 B
};                                 // total 212992 B

extern __shared__ char smem_raw[];

__device__ __forceinline__ void grid_sync(unsigned& target) {
    __threadfence();
    __syncthreads();
    target += gridDim.x;
    if (threadIdx.x == 0) {
        atomicAdd(&g_bar, 1u);
        volatile unsigned* p = &g_bar;
        while (*p < target) { __nanosleep(64); }
    }
    __syncthreads();
}

__global__ void __launch_bounds__(128, 1) lstm_persistent(
    const float* __restrict__ h0, const float* __restrict__ c0,
    const int* __restrict__ mask, const float* __restrict__ Wh,
    float* __restrict__ out)
{
    RSmem& S = *reinterpret_cast<RSmem*>(smem_raw);
    const int tid   = threadIdx.x;
    const int lane  = tid & 31;
    const int w     = tid >> 5;          // warp 0..3 -> m16 tile
    const int ci    = blockIdx.x;
    const int jbase = ci * 8;

    // ---- load Wh slice, split to bf16 hi/lo (resident all steps)
    for (int i = 0; i < 256; ++i) {
        int e = i * 128 + tid;           // 32768 elements
        int n = e >> 10, k = e & 1023;
        int grow = (n >> 3) * HH + jbase + (n & 7);
        float v = Wh[(size_t)grow * HH + k];
        __nv_bfloat16 h = __float2bfloat16_rn(v);
        float r = v - __bfloat162float(h);
        S.whH[n][k] = h;
        S.whL[n][k] = __float2bfloat16_rn(r);
    }
    // ---- init h / own-c state
    for (int p = tid; p < 512; p += 128) {
        int b = p >> 3, jj = p & 7;
        S.hs[b][jj] = h0[b * HH + jbase + jj];
        S.cs[b][jj] = c0[b * HH + jbase + jj];
    }
    __syncthreads();

    const uint32_t aH_base = sh_addr(&S.cH[w * 16 + (lane & 15)][(lane >> 4) * 8]);
    const uint32_t aL_base = sh_addr(&S.cL[w * 16 + (lane & 15)][(lane >> 4) * 8]);
    const uint32_t bH_base = sh_addr(&S.whH[lane & 7][(lane >> 3) * 8]);
    const uint32_t bL_base = sh_addr(&S.whL[lane & 7][(lane >> 3) * 8]);

    unsigned bar_target = 0;

    for (int t = 0; t < TT; ++t) {
        // ---- prefetch x4 + mask
        float x4v[4][4];
        int   mv[4];
#pragma unroll
        for (int r = 0; r < 4; ++r) {
            int p = tid + 128 * r;
            int b = p >> 3, jj = p & 7;
            const float* xp = g_x4 + ((size_t)t * BB + b) * GG + jbase + jj;
            x4v[r][0] = xp[0];
            x4v[r][1] = xp[HH];
            x4v[r][2] = xp[2 * HH];
            x4v[r][3] = xp[3 * HH];
            mv[r] = mask[t * BB + b];
        }

        const uint4* csrc = (const uint4*)(g_cpk[t & 1]);   // [64][256] uint4
        float acc[4][4];
#pragma unroll
        for (int nt = 0; nt < 4; ++nt)
#pragma unroll
            for (int e = 0; e < 4; ++e) acc[nt][e] = 0.f;

        for (int kc = 0; kc < 4; ++kc) {
            __syncthreads();   // previous chunk's mma done before overwrite
            // ---- unpack packed c chunk into cH / cL (bf16)
#pragma unroll 4
            for (int j2 = 0; j2 < 32; ++j2) {
                int u = tid + 128 * j2;
                int row = u >> 6, k4 = u & 63;
                uint4 v = __ldcg(&csrc[row * 256 + kc * 64 + k4]);
                unsigned h01 = __byte_perm(v.x, v.y, 0x7632);
                unsigned l01 = __byte_perm(v.x, v.y, 0x5410);
                unsigned h23 = __byte_perm(v.z, v.w, 0x7632);
                unsigned l23 = __byte_perm(v.z, v.w, 0x5410);
                *(uint2*)&S.cH[row][k4 * 4] = make_uint2(h01, h23);
                *(uint2*)&S.cL[row][k4 * 4] = make_uint2(l01, l23);
            }
            __syncthreads();

            // ---- tensor-core products over this K chunk
#pragma unroll
            for (int g = 0; g < 8; ++g) {
                uint32_t ah0[4], ah1[4], al0[4], al1[4];
                LDSM_X4(ah0, aH_base + (uint32_t)(g * 32) * 2);
                LDSM_X4(ah1, aH_base + (uint32_t)(g * 32 + 16) * 2);
                LDSM_X4(al0, aL_base + (uint32_t)(g * 32) * 2);
                LDSM_X4(al1, aL_base + (uint32_t)(g * 32 + 16) * 2);
                const uint32_t koff = (uint32_t)((kc * 256 + g * 32) * 2);
#pragma unroll
                for (int nt = 0; nt < 4; ++nt) {
                    uint32_t bh[4], bl[4];
                    LDSM_X4(bh, bH_base + (uint32_t)(nt * 8 * 1032) * 2 + koff);
                    LDSM_X4(bl, bL_base + (uint32_t)(nt * 8 * 1032) * 2 + koff);
                    MMA_BF16(acc[nt], ah0, bh[0], bh[1]);
                    MMA_BF16(acc[nt], ah1, bh[2], bh[3]);
                    MMA_BF16(acc[nt], al0, bh[0], bh[1]);
                    MMA_BF16(acc[nt], al1, bh[2], bh[3]);
                    MMA_BF16(acc[nt], ah0, bl[0], bl[1]);
                    MMA_BF16(acc[nt], ah1, bl[2], bl[3]);
                }
            }
        }

        // ---- stage pre-activations through smem
        {
            int prow = w * 16 + (lane >> 2);
            int pcol = (lane & 3) * 2;
#pragma unroll
            for (int nt = 0; nt < 4; ++nt) {
                S.pre[prow][nt * 8 + pcol]         = acc[nt][0];
                S.pre[prow][nt * 8 + pcol + 1]     = acc[nt][1];
                S.pre[prow + 8][nt * 8 + pcol]     = acc[nt][2];
                S.pre[prow + 8][nt * 8 + pcol + 1] = acc[nt][3];
            }
        }
        __syncthreads();

        // ---- gates + state update + publish
        unsigned* cdst = g_cpk[(t + 1) & 1];
#pragma unroll
        for (int r = 0; r < 4; ++r) {
            int p = tid + 128 * r;
            int b = p >> 3, jj = p & 7;
            int jcol = jbase + jj;

            float pi = S.pre[b][jj]      + x4v[r][0];
            float pf = S.pre[b][8 + jj]  + x4v[r][1];
            float po = S.pre[b][16 + jj] + x4v[r][2];
            float pg = S.pre[b][24 + jj] + x4v[r][3];

            float ig = 1.f / (1.f + __expf(-pi));
            float fg = 1.f / (1.f + __expf(-pf));
            float og = 1.f / (1.f + __expf(-po));
            float gg = tanhf(pg);

            float cold = S.cs[b][jj];
            float cnew = fg * cold + ig * gg;
            float hold = S.hs[b][jj];
            int   m    = mv[r];
            float hnew = m ? (og * tanhf(cnew)) : hold;
            float cpub = m ? cnew : cold;

            S.hs[b][jj] = hnew;
            S.cs[b][jj] = cpub;
            cdst[b * HH + jcol] = pack_split(cpub);
            out[((size_t)t * BB + b) * HH + jcol] = hnew;
        }

        grid_sync(bar_target);
    }

    // ---- finals: h_last, c_last appended after hiddens
    const size_t hid_elems = (size_t)TT * BB * HH;
    for (int p = tid; p < 512; p += 128) {
        int b = p >> 3, jj = p & 7;
        out[hid_elems + b * HH + jbase + jj]           = S.hs[b][jj];
        out[hid_elems + BB * HH + b * HH + jbase + jj] = S.cs[b][jj];
    }
}

// ------------------------------------------------------------------
// Launch
// ------------------------------------------------------------------
extern "C" void kernel_launch(void* const* d_in, const int* in_sizes, int n_in,
                              void* d_out, int out_size) {
    const float* X    = (const float*)d_in[0];
    const float* h0   = (const float*)d_in[1];
    const float* c0   = (const float*)d_in[2];
    const int*   mask = (const int*)d_in[3];
    const float* Wx   = (const float*)d_in[4];
    const float* Wh   = (const float*)d_in[5];
    const float* bias = (const float*)d_in[6];
    float* out = (float*)d_out;

    cudaFuncSetAttribute(lstm_persistent,
                         cudaFuncAttributeMaxDynamicSharedMemorySize,
                         (int)sizeof(RSmem));

    init_kernel<<<256, 256>>>(c0);

    split_x_kernel<<<(TT * BB * KIN / 4 + 255) / 256, 256>>>(X);
    split_w_kernel<<<(GG * KIN / 4 + 255) / 256, 256>>>(Wx);

    dim3 g(GG / 128, (TT * BB) / 128);   // (32, 256)
    x4_mma_kernel<<<g, 256>>>(bias);

    lstm_persistent<<<128, 128, sizeof(RSmem)>>>(h0, c0, mask, Wh, out);
}

// round 6
// speedup vs baseline: 2.7967x; 1.4986x over previous
#include <cuda_runtime.h>
#include <cuda_bf16.h>
#include <math.h>
#include <stdint.h>

#define TT 512
#define BB 64
#define KIN 1024
#define HH 1024
#define GG 4096   // 4*H

// ------------------------------------------------------------------
// Scratch (device globals: allocation is forbidden in kernel_launch)
// ------------------------------------------------------------------
__device__ float         g_x4[(size_t)TT * BB * GG];     // 512 MB fp32: X@Wx^T + b
__device__ __nv_bfloat16 g_xh[(size_t)TT * BB * KIN];    // X hi split
__device__ __nv_bfloat16 g_xl[(size_t)TT * BB * KIN];    // X lo split
__device__ __nv_bfloat16 g_wxh[(size_t)GG * KIN];        // Wx hi
__device__ __nv_bfloat16 g_wxl[(size_t)GG * KIN];        // Wx lo
__device__ unsigned      g_cpk[2][BB * HH];              // packed (hi<<16)|lo cell state
__device__ unsigned      g_bar;

// ------------------------------------------------------------------
// helpers
// ------------------------------------------------------------------
__device__ __forceinline__ unsigned pack_split(float v) {
    __nv_bfloat16 h = __float2bfloat16_rn(v);
    float r = v - __bfloat162float(h);
    __nv_bfloat16 l = __float2bfloat16_rn(r);
    return ((unsigned)__bfloat16_as_ushort(h) << 16) |
           (unsigned)__bfloat16_as_ushort(l);
}

__device__ __forceinline__ uint32_t sh_addr(const void* p) {
    return (uint32_t)__cvta_generic_to_shared(p);
}

#define LDSM_X4(r, addr)                                                     \
    asm volatile("ldmatrix.sync.aligned.m8n8.x4.shared.b16 {%0,%1,%2,%3}, [%4];" \
                 : "=r"((r)[0]), "=r"((r)[1]), "=r"((r)[2]), "=r"((r)[3])    \
                 : "r"(addr))

#define LDSM_X2(r, addr)                                                     \
    asm volatile("ldmatrix.sync.aligned.m8n8.x2.shared.b16 {%0,%1}, [%2];"   \
                 : "=r"((r)[0]), "=r"((r)[1]) : "r"(addr))

#define MMA_BF16(d, a, b0, b1)                                               \
    asm volatile("mma.sync.aligned.m16n8k16.row.col.f32.bf16.bf16.f32 "      \
                 "{%0,%1,%2,%3}, {%4,%5,%6,%7}, {%8,%9}, {%0,%1,%2,%3};"     \
                 : "+f"((d)[0]), "+f"((d)[1]), "+f"((d)[2]), "+f"((d)[3])    \
                 : "r"((a)[0]), "r"((a)[1]), "r"((a)[2]), "r"((a)[3]),       \
                   "r"(b0), "r"(b1))

// ------------------------------------------------------------------
// Init: barrier + seed packed c buffer
// ------------------------------------------------------------------
__global__ void init_kernel(const float* __restrict__ c0) {
    int idx = blockIdx.x * blockDim.x + threadIdx.x;
    if (idx == 0) g_bar = 0u;
    if (idx < BB * HH) g_cpk[0][idx] = pack_split(c0[idx]);
}

// ------------------------------------------------------------------
// Split kernels: fp32 -> (hi, lo) bf16
// ------------------------------------------------------------------
__device__ __forceinline__ void split4_store(const float4* src, uint2* dh,
                                             uint2* dl, int i) {
    float4 v = src[i];
    unsigned p0 = pack_split(v.x), p1 = pack_split(v.y);
    unsigned p2 = pack_split(v.z), p3 = pack_split(v.w);
    dh[i] = make_uint2(__byte_perm(p0, p1, 0x7632), __byte_perm(p2, p3, 0x7632));
    dl[i] = make_uint2(__byte_perm(p0, p1, 0x5410), __byte_perm(p2, p3, 0x5410));
}

__global__ void split_x_kernel(const float* __restrict__ X) {
    int i = blockIdx.x * blockDim.x + threadIdx.x;
    const int n4 = TT * BB * KIN / 4;
    if (i < n4)
        split4_store((const float4*)X, (uint2*)g_xh, (uint2*)g_xl, i);
}

__global__ void split_w_kernel(const float* __restrict__ W) {
    int i = blockIdx.x * blockDim.x + threadIdx.x;
    const int n4 = GG * KIN / 4;
    if (i < n4)
        split4_store((const float4*)W, (uint2*)g_wxh, (uint2*)g_wxl, i);
}

// ------------------------------------------------------------------
// X4 GEMM via tensor cores (bf16 split, 3 phase products)
// (unchanged from R2 — tensor=52.5%; isolated from this round's change)
// ------------------------------------------------------------------
__global__ void __launch_bounds__(256) x4_mma_kernel(const float* __restrict__ bias) {
    __shared__ __align__(16) __nv_bfloat16 SA[128][72];
    __shared__ __align__(16) __nv_bfloat16 SB[128][72];

    const int tid  = threadIdx.x;
    const int lane = tid & 31;
    const int wid  = tid >> 5;
    const int wm   = wid >> 1;
    const int wn   = wid & 1;
    const int m0   = blockIdx.y * 128;
    const int n0   = blockIdx.x * 128;

    float acc[2][8][4];
#pragma unroll
    for (int mi = 0; mi < 2; ++mi)
#pragma unroll
        for (int nt = 0; nt < 8; ++nt)
#pragma unroll
            for (int e = 0; e < 4; ++e) acc[mi][nt][e] = 0.f;

    const uint32_t a_base =
        sh_addr(&SA[wm * 32 + (lane & 15)][(lane >> 4) * 8]);
    const uint32_t b_base =
        sh_addr(&SB[wn * 64 + (lane & 7)][((lane >> 3) & 1) * 8]);

    uint4 av[4], bv[4];
    {
        const __nv_bfloat16* Asrc = g_xh;
        const __nv_bfloat16* Bsrc = g_wxh;
#pragma unroll
        for (int j = 0; j < 4; ++j) {
            int u = tid + 256 * j;
            int row = u >> 3, seg = u & 7;
            av[j] = *(const uint4*)(Asrc + (size_t)(m0 + row) * KIN + seg * 8);
            bv[j] = *(const uint4*)(Bsrc + (size_t)(n0 + row) * KIN + seg * 8);
        }
    }

    for (int kc2 = 0; kc2 < 48; ++kc2) {
        __syncthreads();
#pragma unroll
        for (int j = 0; j < 4; ++j) {
            int u = tid + 256 * j;
            int row = u >> 3, seg = u & 7;
            *(uint4*)&SA[row][seg * 8] = av[j];
            *(uint4*)&SB[row][seg * 8] = bv[j];
        }
        __syncthreads();

        if (kc2 < 47) {
            int nk = kc2 + 1;
            int p  = nk >> 4;
            int kb = (nk & 15) << 6;
            const __nv_bfloat16* Asrc = (p == 1) ? g_xl : g_xh;
            const __nv_bfloat16* Bsrc = (p == 2) ? g_wxl : g_wxh;
#pragma unroll
            for (int j = 0; j < 4; ++j) {
                int u = tid + 256 * j;
                int row = u >> 3, seg = u & 7;
                av[j] = *(const uint4*)(Asrc + (size_t)(m0 + row) * KIN + kb + seg * 8);
                bv[j] = *(const uint4*)(Bsrc + (size_t)(n0 + row) * KIN + kb + seg * 8);
            }
        }

#pragma unroll
        for (int ks = 0; ks < 4; ++ks) {
            uint32_t a[2][4];
            LDSM_X4(a[0], a_base + (uint32_t)(ks * 16) * 2);
            LDSM_X4(a[1], a_base + (uint32_t)(16 * 72 + ks * 16) * 2);
            uint32_t b[8][2];
#pragma unroll
            for (int nt = 0; nt < 8; ++nt)
                LDSM_X2(b[nt], b_base + (uint32_t)(nt * 8 * 72 + ks * 16) * 2);
#pragma unroll
            for (int mi = 0; mi < 2; ++mi)
#pragma unroll
                for (int nt = 0; nt < 8; ++nt)
                    MMA_BF16(acc[mi][nt], a[mi], b[nt][0], b[nt][1]);
        }
    }

    const int r0  = m0 + wm * 32 + (lane >> 2);
    const int c0c = n0 + wn * 64 + (lane & 3) * 2;
#pragma unroll
    for (int nt = 0; nt < 8; ++nt) {
        float2 bv2 = *(const float2*)&bias[c0c + nt * 8];
#pragma unroll
        for (int mi = 0; mi < 2; ++mi) {
            float* o = g_x4 + (size_t)(r0 + mi * 16) * GG + c0c + nt * 8;
            float2 v0 = make_float2(acc[mi][nt][0] + bv2.x, acc[mi][nt][1] + bv2.y);
            float2 v1 = make_float2(acc[mi][nt][2] + bv2.x, acc[mi][nt][3] + bv2.y);
            *(float2*)o            = v0;
            *(float2*)(o + 8 * GG) = v1;
        }
    }
}

// ------------------------------------------------------------------
// Persistent recurrence kernel, v2:
// 128 CTAs x 256 threads (8 warps: 4 m-slices x 2 n-halves).
// Double-buffered Kc=128 c-chunks; split-phase grid barrier.
// ------------------------------------------------------------------
#define KC 128
#define NCHUNK (HH / KC)          // 8

struct RSmem {
    __nv_bfloat16 whH[32][1032];     // 66048 B
    __nv_bfloat16 whL[32][1032];     // 66048 B
    __nv_bfloat16 cH[2][64][KC + 8]; // 34816 B (double-buffered chunk)
    __nv_bfloat16 cL[2][64][KC + 8]; // 34816 B
    float pre[64][36];               //  9216 B
    float hs[64][8];                 //  2048 B
    float cs[64][8];                 //  2048 B
};                                   // 215040 B

#define CBUF_BYTES (64 * (KC + 8) * 2)   // 17408 per buffer

extern __shared__ char smem_raw[];

__global__ void __launch_bounds__(256, 1) lstm_persistent(
    const float* __restrict__ h0, const float* __restrict__ c0,
    const int* __restrict__ mask, const float* __restrict__ Wh,
    float* __restrict__ out)
{
    RSmem& S = *reinterpret_cast<RSmem*>(smem_raw);
    const int tid   = threadIdx.x;
    const int lane  = tid & 31;
    const int w     = tid >> 5;      // warp 0..7
    const int wm    = w & 3;         // m-slice (16 batch rows)
    const int wn    = w >> 2;        // n-half  (16 of 32 cols)
    const int ci    = blockIdx.x;
    const int jbase = ci * 8;

    // ---- load Wh slice, split to bf16 hi/lo (resident all steps)
    for (int i = 0; i < 128; ++i) {
        int e = i * 256 + tid;           // 32768 elements
        int n = e >> 10, k = e & 1023;
        int grow = (n >> 3) * HH + jbase + (n & 7);
        float v = Wh[(size_t)grow * HH + k];
        __nv_bfloat16 h = __float2bfloat16_rn(v);
        float r = v - __bfloat162float(h);
        S.whH[n][k] = h;
        S.whL[n][k] = __float2bfloat16_rn(r);
    }
    // ---- init h / own-c state
    for (int p = tid; p < 512; p += 256) {
        int b = p >> 3, jj = p & 7;
        S.hs[b][jj] = h0[b * HH + jbase + jj];
        S.cs[b][jj] = c0[b * HH + jbase + jj];
    }
    __syncthreads();

    const uint32_t aH_base =
        sh_addr(&S.cH[0][wm * 16 + (lane & 15)][(lane >> 4) * 8]);
    const uint32_t aL_base =
        sh_addr(&S.cL[0][wm * 16 + (lane & 15)][(lane >> 4) * 8]);
    const uint32_t bH_base =
        sh_addr(&S.whH[wn * 16 + (lane & 7)][(lane >> 3) * 8]);
    const uint32_t bL_base =
        sh_addr(&S.whL[wn * 16 + (lane & 7)][(lane >> 3) * 8]);

    unsigned bar_target = 0;

    // ---- prefetch x4 + mask for step 0
    float x4v[2][4];
    int   mv[2];
#pragma unroll
    for (int r = 0; r < 2; ++r) {
        int p = tid + 256 * r;
        int b = p >> 3, jj = p & 7;
        const float* xp = g_x4 + ((size_t)0 * BB + b) * GG + jbase + jj;
        x4v[r][0] = xp[0];
        x4v[r][1] = xp[HH];
        x4v[r][2] = xp[2 * HH];
        x4v[r][3] = xp[3 * HH];
        mv[r] = mask[0 * BB + b];
    }

    for (int t = 0; t < TT; ++t) {
        const uint4* csrc = (const uint4*)(g_cpk[t & 1]);   // [64][256] uint4

        // per-thread fixed unpack coordinates: row = w + 8*j2, k4 = lane
        // prologue: LDG chunk 0
        uint4 v[8];
#pragma unroll
        for (int j2 = 0; j2 < 8; ++j2)
            v[j2] = __ldcg(&csrc[(w + 8 * j2) * 256 + lane]);

        float acc[2][4];
#pragma unroll
        for (int nt = 0; nt < 2; ++nt)
#pragma unroll
            for (int e = 0; e < 4; ++e) acc[nt][e] = 0.f;

#pragma unroll
        for (int kc = 0; kc < NCHUNK; ++kc) {
            const int buf = kc & 1;
            __syncthreads();   // buffer `buf` free (MMA of kc-2 done)

            // ---- unpack regs -> smem chunk buffer
#pragma unroll
            for (int j2 = 0; j2 < 8; ++j2) {
                int row = w + 8 * j2;
                unsigned h01 = __byte_perm(v[j2].x, v[j2].y, 0x7632);
                unsigned l01 = __byte_perm(v[j2].x, v[j2].y, 0x5410);
                unsigned h23 = __byte_perm(v[j2].z, v[j2].w, 0x7632);
                unsigned l23 = __byte_perm(v[j2].z, v[j2].w, 0x5410);
                *(uint2*)&S.cH[buf][row][lane * 4] = make_uint2(h01, h23);
                *(uint2*)&S.cL[buf][row][lane * 4] = make_uint2(l01, l23);
            }
            // ---- issue LDG for next chunk (overlaps with MMA below)
            if (kc < NCHUNK - 1) {
#pragma unroll
                for (int j2 = 0; j2 < 8; ++j2)
                    v[j2] = __ldcg(&csrc[(w + 8 * j2) * 256 + (kc + 1) * 32 + lane]);
            }
            __syncthreads();

            // ---- tensor-core products over this chunk (all 8 warps)
            const uint32_t abuf = (uint32_t)(buf * CBUF_BYTES);
#pragma unroll
            for (int g = 0; g < KC / 32; ++g) {
                uint32_t ah0[4], ah1[4], al0[4], al1[4];
                LDSM_X4(ah0, aH_base + abuf + (uint32_t)(g * 32) * 2);
                LDSM_X4(ah1, aH_base + abuf + (uint32_t)(g * 32 + 16) * 2);
                LDSM_X4(al0, aL_base + abuf + (uint32_t)(g * 32) * 2);
                LDSM_X4(al1, aL_base + abuf + (uint32_t)(g * 32 + 16) * 2);
                const uint32_t koff = (uint32_t)((kc * KC + g * 32) * 2);
#pragma unroll
                for (int nt = 0; nt < 2; ++nt) {
                    uint32_t bh[4], bl[4];
                    LDSM_X4(bh, bH_base + (uint32_t)(nt * 8 * 1032) * 2 + koff);
                    LDSM_X4(bl, bL_base + (uint32_t)(nt * 8 * 1032) * 2 + koff);
                    MMA_BF16(acc[nt], ah0, bh[0], bh[1]);
                    MMA_BF16(acc[nt], ah1, bh[2], bh[3]);
                    MMA_BF16(acc[nt], al0, bh[0], bh[1]);
                    MMA_BF16(acc[nt], al1, bh[2], bh[3]);
                    MMA_BF16(acc[nt], ah0, bl[0], bl[1]);
                    MMA_BF16(acc[nt], ah1, bl[2], bl[3]);
                }
            }
        }

        // ---- stage pre-activations through smem
        {
            int prow = wm * 16 + (lane >> 2);
            int pcol = (lane & 3) * 2;
#pragma unroll
            for (int nt = 0; nt < 2; ++nt) {
                int cb = (wn * 2 + nt) * 8 + pcol;
                S.pre[prow][cb]         = acc[nt][0];
                S.pre[prow][cb + 1]     = acc[nt][1];
                S.pre[prow + 8][cb]     = acc[nt][2];
                S.pre[prow + 8][cb + 1] = acc[nt][3];
            }
        }
        __syncthreads();

        // ---- gates + state update + publish c
        unsigned* cdst = g_cpk[(t + 1) & 1];
        float hv[2];
#pragma unroll
        for (int r = 0; r < 2; ++r) {
            int p = tid + 256 * r;
            int b = p >> 3, jj = p & 7;
            int jcol = jbase + jj;

            float pi = S.pre[b][jj]      + x4v[r][0];
            float pf = S.pre[b][8 + jj]  + x4v[r][1];
            float po = S.pre[b][16 + jj] + x4v[r][2];
            float pg = S.pre[b][24 + jj] + x4v[r][3];

            float ig = 1.f / (1.f + __expf(-pi));
            float fg = 1.f / (1.f + __expf(-pf));
            float og = 1.f / (1.f + __expf(-po));
            float gg = tanhf(pg);

            float cold = S.cs[b][jj];
            float cnew = fg * cold + ig * gg;
            float hold = S.hs[b][jj];
            int   m    = mv[r];
            float hnew = m ? (og * tanhf(cnew)) : hold;
            float cpub = m ? cnew : cold;

            S.hs[b][jj] = hnew;
            S.cs[b][jj] = cpub;
            hv[r] = hnew;
            cdst[b * HH + jcol] = pack_split(cpub);
        }

        // ---- split-phase grid barrier: arrive, hide work, then wait
        __threadfence();
        __syncthreads();
        bar_target += gridDim.x;
        if (tid == 0) atomicAdd(&g_bar, 1u);

        // hidden work: write h outputs + prefetch next step's x4/mask
#pragma unroll
        for (int r = 0; r < 2; ++r) {
            int p = tid + 256 * r;
            int b = p >> 3, jj = p & 7;
            out[((size_t)t * BB + b) * HH + jbase + jj] = hv[r];
        }
        if (t + 1 < TT) {
#pragma unroll
            for (int r = 0; r < 2; ++r) {
                int p = tid + 256 * r;
                int b = p >> 3, jj = p & 7;
                const float* xp =
                    g_x4 + ((size_t)(t + 1) * BB + b) * GG + jbase + jj;
                x4v[r][0] = xp[0];
                x4v[r][1] = xp[HH];
                x4v[r][2] = xp[2 * HH];
                x4v[r][3] = xp[3 * HH];
                mv[r] = mask[(t + 1) * BB + b];
            }
        }

        if (tid == 0) {
            volatile unsigned* p = &g_bar;
            while (*p < bar_target) { __nanosleep(32); }
        }
        __syncthreads();
    }

    // ---- finals: h_last, c_last appended after hiddens
    const size_t hid_elems = (size_t)TT * BB * HH;
    for (int p = tid; p < 512; p += 256) {
        int b = p >> 3, jj = p & 7;
        out[hid_elems + b * HH + jbase + jj]           = S.hs[b][jj];
        out[hid_elems + BB * HH + b * HH + jbase + jj] = S.cs[b][jj];
    }
}

// ------------------------------------------------------------------
// Launch
// ------------------------------------------------------------------
extern "C" void kernel_launch(void* const* d_in, const int* in_sizes, int n_in,
                              void* d_out, int out_size) {
    const float* X    = (const float*)d_in[0];
    const float* h0   = (const float*)d_in[1];
    const float* c0   = (const float*)d_in[2];
    const int*   mask = (const int*)d_in[3];
    const float* Wx   = (const float*)d_in[4];
    const float* Wh   = (const float*)d_in[5];
    const float* bias = (const float*)d_in[6];
    float* out = (float*)d_out;

    cudaFuncSetAttribute(lstm_persistent,
                         cudaFuncAttributeMaxDynamicSharedMemorySize,
                         (int)sizeof(RSmem));

    init_kernel<<<256, 256>>>(c0);

    split_x_kernel<<<(TT * BB * KIN / 4 + 255) / 256, 256>>>(X);
    split_w_kernel<<<(GG * KIN / 4 + 255) / 256, 256>>>(Wx);

    dim3 g(GG / 128, (TT * BB) / 128);   // (32, 256)
    x4_mma_kernel<<<g, 256>>>(bias);

    lstm_persistent<<<128, 256, sizeof(RSmem)>>>(h0, c0, mask, Wh, out);
}